// round 5
// baseline (speedup 1.0000x reference)
#include <cuda_runtime.h>

// Problem dims
#define B_  64
#define T_  2048
#define E_  256
#define A_  128
#define P_  128
#define R_  1024
#define D_  1024
#define H_  256
#define F_  32
#define KS_ 31
#define PAD_ 15

// ---------------- scratch (no allocations allowed) ----------------
__device__ float g_gates[B_ * 4096];
__device__ float g_ah[B_ * R_];
__device__ float g_ac[B_ * R_];
__device__ float g_pq[B_ * A_];
__device__ float g_energies[B_ * T_];
__device__ float g_ctx[B_ * E_];
__device__ float g_dh[B_ * D_];
__device__ float g_dc[B_ * D_];

// ---------------- fused 3-segment GEMM: C[64,N] = sum_s x_s @ W_s^T + b1 + b2
// x_s: [64, K_s] row-major (contiguous). W_s: rows of length K_s with stride ldW_s.
__global__ __launch_bounds__(256) void gemm3_kernel(
    const float* __restrict__ x1, const float* __restrict__ W1, int K1, int ldW1,
    const float* __restrict__ x2, const float* __restrict__ W2, int K2, int ldW2,
    const float* __restrict__ x3, const float* __restrict__ W3, int K3, int ldW3,
    const float* __restrict__ b1, const float* __restrict__ b2,
    float* __restrict__ C, int N)
{
    __shared__ float As[64][33];   // [m][k]
    __shared__ float Bs[32][34];   // [k][n], padded

    const int tid = threadIdx.x;
    const int tx = tid & 15;       // n-group (2 cols)
    const int ty = tid >> 4;       // m-group (4 rows)
    const int n0 = blockIdx.x * 32;

    float acc[4][2] = {};

#pragma unroll
    for (int s = 0; s < 3; s++) {
        const float* x  = (s == 0) ? x1 : (s == 1) ? x2 : x3;
        const float* W  = (s == 0) ? W1 : (s == 1) ? W2 : W3;
        const int K     = (s == 0) ? K1 : (s == 1) ? K2 : K3;
        const int ldW   = (s == 0) ? ldW1 : (s == 1) ? ldW2 : ldW3;
        if (K == 0) continue;
        for (int k0 = 0; k0 < K; k0 += 32) {
            // load A tile 64x32 (coalesced, conflict-free store with pad 33)
#pragma unroll
            for (int r = 0; r < 8; r++) {
                int idx = tid + r * 256;
                int m = idx >> 5, k = idx & 31;
                As[m][k] = x[(size_t)m * K + k0 + k];
            }
            // load B tile 32(n)x32(k)
#pragma unroll
            for (int r = 0; r < 4; r++) {
                int idx = tid + r * 256;
                int n = idx >> 5, k = idx & 31;
                int nn = n0 + n;
                Bs[k][n] = (nn < N) ? W[(size_t)nn * ldW + k0 + k] : 0.f;
            }
            __syncthreads();
#pragma unroll
            for (int k = 0; k < 32; k++) {
                float2 bv = *(const float2*)&Bs[k][tx * 2];
#pragma unroll
                for (int i = 0; i < 4; i++) {
                    float a = As[ty * 4 + i][k];
                    acc[i][0] += a * bv.x;
                    acc[i][1] += a * bv.y;
                }
            }
            __syncthreads();
        }
    }

#pragma unroll
    for (int i = 0; i < 4; i++) {
        int m = ty * 4 + i;
#pragma unroll
        for (int j = 0; j < 2; j++) {
            int n = n0 + tx * 2 + j;
            if (n < N) {
                float v = acc[i][j];
                if (b1) v += b1[n];
                if (b2) v += b2[n];
                C[(size_t)m * N + n] = v;
            }
        }
    }
}

// ---------------- LSTM pointwise ----------------
__device__ __forceinline__ float sigm(float x) { return 1.f / (1.f + __expf(-x)); }

__global__ void lstm_pointwise(const float* __restrict__ gates,
                               const float* __restrict__ c_prev,
                               float* __restrict__ h_out, float* __restrict__ c_out,
                               int Nc)
{
    int idx = blockIdx.x * blockDim.x + threadIdx.x;
    if (idx >= B_ * Nc) return;
    int b = idx / Nc, j = idx - b * Nc;
    const float* g = gates + (size_t)b * 4 * Nc;
    float gi = sigm(g[j]);
    float gf = sigm(g[Nc + j]);
    float gg = tanhf(g[2 * Nc + j]);
    float go = sigm(g[3 * Nc + j]);
    float c2 = gf * c_prev[idx] + gi * gg;
    h_out[idx] = go * tanhf(c2);
    c_out[idx] = c2;
}

// ---------------- fused conv31 + location-fc + energy ----------------
// grid: (T/64, B), block 128 (= A). Computes energies[b, t0..t0+63].
__global__ __launch_bounds__(128) void energies_kernel(
    const float* __restrict__ att_w, const float* __restrict__ att_w_cum,
    const float* __restrict__ pm,    // [B,T,A]
    const float* __restrict__ pq,    // [B,A]
    const float* __restrict__ W_loc, // [F,2,31]
    const float* __restrict__ W_lfc, // [A,F]
    const float* __restrict__ W_v,   // [A]
    float* __restrict__ energies)    // [B,T]
{
    const int b  = blockIdx.y;
    const int t0 = blockIdx.x * 64;
    const int tid = threadIdx.x;

    __shared__ float s_aw[2][94];         // halo: 64 + 2*15
    __shared__ float s_conv[F_][68];      // conv result, padded rows (16B-aligned)
    __shared__ union {
        float wloc[F_][2][KS_];
        float val[64][128];
    } u;

    // halo load (zeros outside [0,T))
    for (int i = tid; i < 94; i += 128) {
        int g = t0 - PAD_ + i;
        bool ok = (g >= 0) && (g < T_);
        s_aw[0][i] = ok ? att_w[b * T_ + g] : 0.f;
        s_aw[1][i] = ok ? att_w_cum[b * T_ + g] : 0.f;
    }
    for (int i = tid; i < F_ * 2 * KS_; i += 128)
        ((float*)u.wloc)[i] = W_loc[i];
    __syncthreads();

    // conv phase: thread -> (f = tid&31, tg = tid>>5), 16 t's each
    {
        int f = tid & 31, tg = tid >> 5;
        float acc[16];
#pragma unroll
        for (int i = 0; i < 16; i++) acc[i] = 0.f;
#pragma unroll
        for (int c = 0; c < 2; c++) {
            float av[46];
#pragma unroll
            for (int i = 0; i < 46; i++) av[i] = s_aw[c][tg * 16 + i];
#pragma unroll
            for (int k = 0; k < KS_; k++) {
                float w = u.wloc[f][c][k];
#pragma unroll
                for (int tt = 0; tt < 16; tt++) acc[tt] += w * av[k + tt];
            }
        }
#pragma unroll
        for (int tt = 0; tt < 16; tt++) s_conv[f][tg * 16 + tt] = acc[tt];
    }
    __syncthreads();

    // la + tanh energy per (t, a=tid); u.wloc is dead now -> u.val
    float r_lfc[F_];
#pragma unroll
    for (int f = 0; f < F_; f++) r_lfc[f] = W_lfc[tid * F_ + f];
    float r_pq = pq[b * A_ + tid];
    float r_wv = W_v[tid];
    const float* pmb = pm + ((size_t)b * T_ + t0) * A_ + tid;

    for (int t4 = 0; t4 < 16; t4++) {
        float la0 = 0, la1 = 0, la2 = 0, la3 = 0;
#pragma unroll
        for (int f = 0; f < F_; f++) {
            float4 c4 = *(const float4*)&s_conv[f][t4 * 4];
            float lf = r_lfc[f];
            la0 += lf * c4.x; la1 += lf * c4.y; la2 += lf * c4.z; la3 += lf * c4.w;
        }
        int t = t4 * 4;
        u.val[t + 0][tid] = tanhf(r_pq + pmb[(size_t)(t + 0) * A_] + la0) * r_wv;
        u.val[t + 1][tid] = tanhf(r_pq + pmb[(size_t)(t + 1) * A_] + la1) * r_wv;
        u.val[t + 2][tid] = tanhf(r_pq + pmb[(size_t)(t + 2) * A_] + la2) * r_wv;
        u.val[t + 3][tid] = tanhf(r_pq + pmb[(size_t)(t + 3) * A_] + la3) * r_wv;
    }
    __syncthreads();

    // reduce over a: warp w handles t = w*16 .. w*16+15
    int wid = tid >> 5, lane = tid & 31;
    for (int i = 0; i < 16; i++) {
        int t = wid * 16 + i;
        float v = u.val[t][lane] + u.val[t][lane + 32] +
                  u.val[t][lane + 64] + u.val[t][lane + 96];
#pragma unroll
        for (int o = 16; o; o >>= 1) v += __shfl_xor_sync(0xffffffffu, v, o);
        if (lane == 0) energies[b * T_ + t0 + t] = v;
    }
}

// ---------------- masked softmax over T (mask is int32: nonzero -> -inf) ----------------
__global__ __launch_bounds__(256) void softmax_kernel(
    const float* __restrict__ energies, const int* __restrict__ mask,
    float* __restrict__ weights)
{
    int b = blockIdx.x, tid = threadIdx.x;
    __shared__ float red[8];
    __shared__ float s_bcast;
    float v[8];
    float mx = -3.4e38f;
#pragma unroll
    for (int r = 0; r < 8; r++) {
        int t = tid + r * 256;
        float e = energies[b * T_ + t];
        if (mask[b * T_ + t] != 0) e = -1e30f;
        v[r] = e;
        mx = fmaxf(mx, e);
    }
#pragma unroll
    for (int o = 16; o; o >>= 1) mx = fmaxf(mx, __shfl_xor_sync(0xffffffffu, mx, o));
    if ((tid & 31) == 0) red[tid >> 5] = mx;
    __syncthreads();
    if (tid < 8) {
        float m = red[tid];
#pragma unroll
        for (int o = 4; o; o >>= 1) m = fmaxf(m, __shfl_xor_sync(0xffu, m, o));
        if (tid == 0) s_bcast = m;
    }
    __syncthreads();
    mx = s_bcast;
    float sum = 0.f;
#pragma unroll
    for (int r = 0; r < 8; r++) { v[r] = __expf(v[r] - mx); sum += v[r]; }
#pragma unroll
    for (int o = 16; o; o >>= 1) sum += __shfl_xor_sync(0xffffffffu, sum, o);
    if ((tid & 31) == 0) red[tid >> 5] = sum;
    __syncthreads();
    if (tid < 8) {
        float m = red[tid];
#pragma unroll
        for (int o = 4; o; o >>= 1) m += __shfl_xor_sync(0xffu, m, o);
        if (tid == 0) s_bcast = m;
    }
    __syncthreads();
    float inv = 1.f / s_bcast;
#pragma unroll
    for (int r = 0; r < 8; r++) weights[b * T_ + tid + r * 256] = v[r] * inv;
}

// ---------------- context: ctx[b,e] = sum_t w[b,t] * memory[b,t,e] ----------------
__global__ void zero_kernel(float* p)
{
    p[blockIdx.x * blockDim.x + threadIdx.x] = 0.f;
}

__global__ __launch_bounds__(256) void ctx_kernel(
    const float* __restrict__ weights, const float* __restrict__ memory,
    float* __restrict__ ctx)
{
    int b = blockIdx.y;
    int t0 = blockIdx.x * 128;
    int e = threadIdx.x;
    const float* mb = memory + ((size_t)b * T_ + t0) * E_ + e;
    const float* wb = weights + b * T_ + t0;
    float acc = 0.f;
#pragma unroll 4
    for (int t = 0; t < 128; t++) acc += wb[t] * mb[(size_t)t * E_];
    atomicAdd(&ctx[b * E_ + e], acc);
}

// ---------------- launch ----------------
extern "C" void kernel_launch(void* const* d_in, const int* in_sizes, int n_in,
                              void* d_out, int out_size)
{
    const float* last_frame = (const float*)d_in[0];
    const float* att_h      = (const float*)d_in[1];
    const float* att_c      = (const float*)d_in[2];
    const float* att_w      = (const float*)d_in[3];
    const float* att_w_cum  = (const float*)d_in[4];
    const float* att_ctx    = (const float*)d_in[5];
    const float* dec_h      = (const float*)d_in[6];
    const float* dec_c      = (const float*)d_in[7];
    const float* memory     = (const float*)d_in[8];
    const float* pmem       = (const float*)d_in[9];
    const float* W_ih_a     = (const float*)d_in[10];
    const float* W_hh_a     = (const float*)d_in[11];
    const float* b_ih_a     = (const float*)d_in[12];
    const float* b_hh_a     = (const float*)d_in[13];
    const float* W_q        = (const float*)d_in[14];
    const float* W_v        = (const float*)d_in[15];
    const float* W_loc      = (const float*)d_in[16];
    const float* W_lfc      = (const float*)d_in[17];
    const float* W_ih_d     = (const float*)d_in[18];
    const float* W_hh_d     = (const float*)d_in[19];
    const float* b_ih_d     = (const float*)d_in[20];
    const float* b_hh_d     = (const float*)d_in[21];
    const float* W_proj     = (const float*)d_in[22];
    const float* b_proj     = (const float*)d_in[23];
    const float* W_gate     = (const float*)d_in[24];
    const float* b_gate     = (const float*)d_in[25];
    const int*   mask       = (const int*)d_in[26];

    float* out = (float*)d_out;
    float* out_proj = out;                      // [64,256]
    float* out_stop = out + B_ * H_;            // [64,1]
    float* out_w    = out + B_ * H_ + B_;       // [64,2048]

    float *gates, *ah, *ac, *pq, *energies, *ctx, *dh, *dc;
    cudaGetSymbolAddress((void**)&gates,    g_gates);
    cudaGetSymbolAddress((void**)&ah,       g_ah);
    cudaGetSymbolAddress((void**)&ac,       g_ac);
    cudaGetSymbolAddress((void**)&pq,       g_pq);
    cudaGetSymbolAddress((void**)&energies, g_energies);
    cudaGetSymbolAddress((void**)&ctx,      g_ctx);
    cudaGetSymbolAddress((void**)&dh,       g_dh);
    cudaGetSymbolAddress((void**)&dc,       g_dc);

    // 1) attention LSTM gates: [last_frame(128) | att_ctx(256)] @ W_ih_a^T + att_h @ W_hh_a^T + biases
    gemm3_kernel<<<128, 256>>>(last_frame, W_ih_a,        P_, P_ + E_,
                               att_ctx,    W_ih_a + P_,   E_, P_ + E_,
                               att_h,      W_hh_a,        R_, R_,
                               b_ih_a, b_hh_a, gates, 4 * R_);
    // 2) attention LSTM cell
    lstm_pointwise<<<(B_ * R_) / 256, 256>>>(gates, att_c, ah, ac, R_);
    // 3) query projection pq = ah @ W_q^T
    gemm3_kernel<<<(A_ + 31) / 32, 256>>>(ah, W_q, R_, R_,
                                          nullptr, nullptr, 0, 0,
                                          nullptr, nullptr, 0, 0,
                                          nullptr, nullptr, pq, A_);
    // 4) conv + location fc + energies
    energies_kernel<<<dim3(T_ / 64, B_), 128>>>(att_w, att_w_cum, pmem, pq,
                                                W_loc, W_lfc, W_v, energies);
    // 5) masked softmax -> weights (directly into d_out)
    softmax_kernel<<<B_, 256>>>(energies, mask, out_w);
    // 6,7) context vector
    zero_kernel<<<B_, E_>>>(ctx);
    ctx_kernel<<<dim3(16, B_), 256>>>(out_w, memory, ctx);
    // 8) decoder LSTM gates: [ah(1024) | ctx(256)] @ W_ih_d^T + dec_h @ W_hh_d^T + biases
    gemm3_kernel<<<128, 256>>>(ah,    W_ih_d,       R_, R_ + E_,
                               ctx,   W_ih_d + R_,  E_, R_ + E_,
                               dec_h, W_hh_d,       D_, D_,
                               b_ih_d, b_hh_d, gates, 4 * D_);
    // 9) decoder LSTM cell
    lstm_pointwise<<<(B_ * D_) / 256, 256>>>(gates, dec_c, dh, dc, D_);
    // 10) decoder output projection
    gemm3_kernel<<<(H_ + 31) / 32, 256>>>(dh,  W_proj,       D_, D_ + E_,
                                          ctx, W_proj + D_,  E_, D_ + E_,
                                          nullptr, nullptr, 0, 0,
                                          b_proj, nullptr, out_proj, H_);
    // 11) stop gate
    gemm3_kernel<<<1, 256>>>(dh,  W_gate,       D_, D_ + E_,
                             ctx, W_gate + D_,  E_, D_ + E_,
                             nullptr, nullptr, 0, 0,
                             b_gate, nullptr, out_stop, 1);
}